// round 1
// baseline (speedup 1.0000x reference)
#include <cuda_runtime.h>
#include <math.h>

// ---------------- problem constants ----------------
#define N_TOT   65536      // B*H*W
#define K_CB    512
#define C_DIM   64
#define B_DIM   64
#define HW      1024

#define TM      64         // rows per CTA
#define THREADS 512
#define WPAD    516        // padded row length (floats) for wT: 516*4=2064B, 16B aligned, bank-safe

// output layout (floats), concatenation of the reference tuple
#define Q_OFF     0ULL                       // [64,64,32,32] = 4194304
#define LOSS_OFF  4194304ULL                 // [64]
#define PERP_OFF  4194368ULL                 // [1]
#define ENC_OFF   4194369ULL                 // [65536,512] = 33554432
#define EIDX_OFF  37748801ULL                // [64,1024]   = 65536
#define DIST_OFF  37814337ULL                // [65536,512] = 33554432
#define OUT_TOTAL 71368769

#define SMEM_BYTES (64*WPAD*4 + 64*64*4 + 512*4 + 64*4 + 64*4)

__device__ int g_idx[N_TOT];

// ---------------- f32x2 helpers ----------------
__device__ __forceinline__ unsigned long long pack2(float x) {
    unsigned long long r;
    asm("mov.b64 %0, {%1, %1};" : "=l"(r) : "f"(x));
    return r;
}
__device__ __forceinline__ void fma2(unsigned long long &d, unsigned long long a, unsigned long long b) {
    asm("fma.rn.f32x2 %0, %1, %2, %3;" : "=l"(d) : "l"(a), "l"(b), "l"(d));
}
__device__ __forceinline__ void unpack2(unsigned long long v, float &lo, float &hi) {
    asm("mov.b64 {%0, %1}, %2;" : "=f"(lo), "=f"(hi) : "l"(v));
}

// ---------------- main kernel: distances + argmin + q_out + encodings + enc_idx ----------------
extern "C" __global__ void __launch_bounds__(THREADS, 1)
vq_main(const float* __restrict__ inputs, const float* __restrict__ weight,
        float* __restrict__ out)
{
    extern __shared__ float smem[];
    float* wT    = smem;                    // [64][WPAD]  weight transposed: wT[c][k]
    float* xs    = wT + 64 * WPAD;          // [64][64]    x tile transposed: xs[c][r]
    float* wnorm = xs + 64 * 64;            // [512]
    float* xnorm = wnorm + 512;             // [64]
    int*   sidx  = (int*)(xnorm + 64);      // [64]

    const int tid = threadIdx.x;
    const int n0  = blockIdx.x * TM;        // first row of this tile (64-aligned -> single batch)
    const int b   = n0 >> 10;
    const int p0  = n0 & (HW - 1);

    // load weight [K,C] row-major -> transposed smem
    for (int i = tid; i < K_CB * C_DIM; i += THREADS) {
        int k = i >> 6, c = i & 63;
        wT[c * WPAD + k] = weight[i];
    }
    // load x tile: inputs[b, c, p0+r] -> xs[c][r]  (coalesced over r)
    const float* xbase = inputs + (size_t)b * (C_DIM * HW) + p0;
    for (int i = tid; i < C_DIM * TM; i += THREADS) {
        int c = i >> 6, r = i & 63;
        xs[c * 64 + r] = xbase[(size_t)c * HW + r];
    }
    __syncthreads();

    // wnorm[k] = sum_c wT[c][k]^2 ; xnorm[r] = sum_c xs[c][r]^2
    {
        float s = 0.f;
        #pragma unroll
        for (int c = 0; c < C_DIM; c++) { float w = wT[c * WPAD + tid]; s = fmaf(w, w, s); }
        wnorm[tid] = s;
    }
    if (tid < TM) {
        float s = 0.f;
        #pragma unroll
        for (int c = 0; c < C_DIM; c++) { float x = xs[c * 64 + tid]; s = fmaf(x, x, s); }
        xnorm[tid] = s;
    }
    __syncthreads();

    // thread tile: 4 rows x 16 codes. tid = rowg*32 + lane; warp = rowg (rows rowg*4..+3)
    const int rowg = tid >> 5;
    const int lane = tid & 31;
    const int kbase = lane * 16;

    unsigned long long acc[4][8];
    #pragma unroll
    for (int r = 0; r < 4; r++)
        #pragma unroll
        for (int j = 0; j < 8; j++) acc[r][j] = 0ULL;

    const float* arow = xs + rowg * 4;
    const char*  bcol = (const char*)(wT + kbase);

    #pragma unroll 8
    for (int c = 0; c < C_DIM; c++) {
        const float4 av = *(const float4*)(arow + c * 64);   // broadcast: 4 row values
        unsigned long long a0 = pack2(av.x), a1 = pack2(av.y), a2 = pack2(av.z), a3 = pack2(av.w);
        const unsigned long long* bp = (const unsigned long long*)(bcol + (size_t)c * (WPAD * 4));
        unsigned long long bb[8];
        #pragma unroll
        for (int j = 0; j < 8; j++) bb[j] = bp[j];           // 16 consecutive codes as 8 pairs
        #pragma unroll
        for (int j = 0; j < 8; j++) {
            fma2(acc[0][j], a0, bb[j]);
            fma2(acc[1][j], a1, bb[j]);
            fma2(acc[2][j], a2, bb[j]);
            fma2(acc[3][j], a3, bb[j]);
        }
    }

    // epilogue: distances (reference rounding: (||x||^2+||e||^2) - 2*z), argmin, scatters
    const float INF = __int_as_float(0x7f800000);
    #pragma unroll
    for (int r = 0; r < 4; r++) {
        const int row = rowg * 4 + r;
        const int n   = n0 + row;
        const float xn = xnorm[row];

        float dv[16];
        #pragma unroll
        for (int j = 0; j < 8; j++) {
            float zlo, zhi; unpack2(acc[r][j], zlo, zhi);
            const int k0 = kbase + 2 * j;
            dv[2*j]   = (xn + wnorm[k0])     - 2.0f * zlo;
            dv[2*j+1] = (xn + wnorm[k0 + 1]) - 2.0f * zhi;
        }

        float best = INF; int bidx = 0;
        #pragma unroll
        for (int j = 0; j < 16; j++) {                 // strict '<' keeps first (lowest) index
            if (dv[j] < best) { best = dv[j]; bidx = kbase + j; }
        }

        float* dptr = out + DIST_OFF + (size_t)n * K_CB + kbase;
        #pragma unroll
        for (int j = 0; j < 16; j++) dptr[j] = dv[j];  // DIST_OFF is odd -> scalar stores

        // warp argmin, jnp.argmin tie-break = lowest index
        #pragma unroll
        for (int off = 16; off > 0; off >>= 1) {
            float ob = __shfl_xor_sync(0xffffffffu, best, off);
            int   oi = __shfl_xor_sync(0xffffffffu, bidx, off);
            if (ob < best || (ob == best && oi < bidx)) { best = ob; bidx = oi; }
        }
        if (lane == 0) {
            sidx[row] = bidx;
            g_idx[n]  = bidx;
            out[EIDX_OFF + (size_t)n] = (float)bidx;
            out[ENC_OFF + (size_t)n * K_CB + bidx] = 1.0f;   // rest pre-zeroed by memset
        }
    }
    __syncthreads();

    // q_out tile (NCHW), straight-through rounding replicated: x + (q - x)
    float* qbase = out + (size_t)b * (C_DIM * HW) + p0;
    for (int i = tid; i < C_DIM * TM; i += THREADS) {
        int c = i >> 6, p = i & 63;
        float x = xs[c * 64 + p];
        float q = wT[c * WPAD + sidx[p]];
        qbase[(size_t)c * HW + p] = x + (q - x);
    }
}

// ---------------- loss kernel: loss[b] = 1.25 * mean((q - x)^2) ----------------
extern "C" __global__ void vq_loss(const float* __restrict__ inputs,
                                   const float* __restrict__ weight,
                                   float* __restrict__ out)
{
    __shared__ float red[256];
    const int b = blockIdx.x, tid = threadIdx.x;
    const float* xb = inputs + (size_t)b * (C_DIM * HW);
    const int*   ib = g_idx + b * HW;

    float s = 0.f;
    for (int i = tid; i < C_DIM * HW; i += 256) {
        int p = i & (HW - 1);        // i = c*1024 + p
        int c = i >> 10;
        float x = xb[i];
        float q = weight[ib[p] * C_DIM + c];
        float d = q - x;
        s = fmaf(d, d, s);
    }
    red[tid] = s; __syncthreads();
    for (int off = 128; off > 0; off >>= 1) {
        if (tid < off) red[tid] += red[tid + off];
        __syncthreads();
    }
    if (tid == 0) out[LOSS_OFF + b] = 1.25f * (red[0] * (1.0f / 65536.0f));
}

// ---------------- perplexity kernel (deterministic: integer smem atomics) ----------------
extern "C" __global__ void vq_perp(float* __restrict__ out)
{
    __shared__ int   hist[K_CB];
    __shared__ float red[K_CB];
    const int tid = threadIdx.x;
    hist[tid] = 0;
    __syncthreads();
    for (int i = tid; i < N_TOT; i += K_CB) atomicAdd(&hist[g_idx[i]], 1);
    __syncthreads();
    float p = (float)hist[tid] * (1.0f / 65536.0f);
    red[tid] = -p * logf(p + 1e-10f);
    __syncthreads();
    for (int off = 256; off > 0; off >>= 1) {
        if (tid < off) red[tid] += red[tid + off];
        __syncthreads();
    }
    if (tid == 0) out[PERP_OFF] = expf(red[0]);
}

// ---------------- launch ----------------
extern "C" void kernel_launch(void* const* d_in, const int* in_sizes, int n_in,
                              void* d_out, int out_size)
{
    const float* inputs = (const float*)d_in[0];
    const float* weight = (const float*)d_in[1];
    float* out = (float*)d_out;

    if (out_size != OUT_TOTAL) return;  // layout mismatch -> fail loudly (no OOB writes)

    cudaFuncSetAttribute(vq_main, cudaFuncAttributeMaxDynamicSharedMemorySize, SMEM_BYTES);

    // zero the one-hot encodings region (graph-capturable memset node)
    cudaMemsetAsync(out + ENC_OFF, 0, (size_t)33554432 * sizeof(float), 0);

    vq_main<<<N_TOT / TM, THREADS, SMEM_BYTES>>>(inputs, weight, out);
    vq_loss<<<B_DIM, 256>>>(inputs, weight, out);
    vq_perp<<<1, K_CB>>>(out);
}

// round 2
// speedup vs baseline: 2.6628x; 2.6628x over previous
#include <cuda_runtime.h>
#include <math.h>

// ---------------- problem constants ----------------
#define N_TOT   65536      // B*H*W
#define K_CB    512
#define C_DIM   64
#define B_DIM   64
#define HW      1024

#define TM      64         // rows per CTA
#define THREADS 512
#define WROW    514        // wT row stride (floats): bank stride 2 (2-way STS on transpose only),
                           // even -> 8B alignment for LDS.64 in mainloop

// output layout (floats), concatenation of the reference tuple
#define Q_OFF     0ULL                       // [64,64,32,32] = 4194304
#define LOSS_OFF  4194304ULL                 // [64]
#define PERP_OFF  4194368ULL                 // [1]
#define ENC_OFF   4194369ULL                 // [65536,512] = 33554432
#define EIDX_OFF  37748801ULL                // [64,1024]   = 65536
#define DIST_OFF  37814337ULL                // [65536,512] = 33554432
#define OUT_TOTAL 71368769

// smem layout (floats)
#define SM_WT   0
#define SM_XS   (64*WROW)            // [64][64]
#define SM_WN   (SM_XS + 64*64)      // wnorm[512]
#define SM_XN   (SM_WN + 512)        // xnorm[64]
#define SM_SIDX (SM_XN + 64)         // int sidx[64]
#define SM_CANB (SM_SIDX + 64)       // float candb[128]  (row*2+kg)
#define SM_CANI (SM_CANB + 128)      // int   candi[128]
#define SM_RED  (SM_CANI + 128)      // float red[512]
#define SM_TOTF (SM_RED + 512)
#define SMEM_BYTES (SM_TOTF*4)

__device__ int   g_idx[N_TOT];
__device__ float g_lpart[N_TOT / TM];

// ---------------- f32x2 helpers ----------------
__device__ __forceinline__ unsigned long long pack2(float x) {
    unsigned long long r;
    asm("mov.b64 %0, {%1, %1};" : "=l"(r) : "f"(x));
    return r;
}
__device__ __forceinline__ void fma2(unsigned long long &d, unsigned long long a, unsigned long long b) {
    asm("fma.rn.f32x2 %0, %1, %2, %3;" : "=l"(d) : "l"(a), "l"(b), "l"(d));
}
__device__ __forceinline__ void unpack2(unsigned long long v, float &lo, float &hi) {
    asm("mov.b64 {%0, %1}, %2;" : "=f"(lo), "=f"(hi) : "l"(v));
}

// ---------------- main kernel ----------------
extern "C" __global__ void __launch_bounds__(THREADS, 1)
vq_main(const float* __restrict__ inputs, const float* __restrict__ weight,
        float* __restrict__ out)
{
    extern __shared__ float smem[];
    float* wT    = smem + SM_WT;     // wT[c][k], row stride WROW
    float* xs    = smem + SM_XS;     // xs[c][r]
    float* wnorm = smem + SM_WN;
    float* xnorm = smem + SM_XN;
    int*   sidx  = (int*)(smem + SM_SIDX);
    float* candb = smem + SM_CANB;
    int*   candi = (int*)(smem + SM_CANI);
    float* red   = smem + SM_RED;

    const int tid = threadIdx.x;
    const int n0  = blockIdx.x * TM;        // tile start (64-aligned -> single batch)
    const int b   = n0 >> 10;
    const int p0  = n0 & (HW - 1);

    // load weight [K,C] row-major -> transposed smem (coalesced gmem; 2-way STS conflict only)
    for (int i = tid; i < K_CB * C_DIM; i += THREADS) {
        int k = i >> 6, c = i & 63;
        wT[c * WROW + k] = weight[i];
    }
    // load x tile: inputs[b, c, p0+r] -> xs[c][r] (coalesced over r)
    const float* xbase = inputs + (size_t)b * (C_DIM * HW) + p0;
    for (int i = tid; i < C_DIM * TM; i += THREADS) {
        int c = i >> 6, r = i & 63;
        xs[c * 64 + r] = xbase[(size_t)c * HW + r];
    }
    __syncthreads();

    // wnorm[k] = sum_c wT[c][k]^2 ; xnorm[r] = sum_c xs[c][r]^2
    {
        float s = 0.f;
        #pragma unroll
        for (int c = 0; c < C_DIM; c++) { float w = wT[c * WROW + tid]; s = fmaf(w, w, s); }
        wnorm[tid] = s;
    }
    if (tid < TM) {
        float s = 0.f;
        #pragma unroll
        for (int c = 0; c < C_DIM; c++) { float x = xs[c * 64 + tid]; s = fmaf(x, x, s); }
        xnorm[tid] = s;
    }
    __syncthreads();

    // thread tile: 8 rows x 8 codes (4 f32x2 pairs), conflict-free k mapping
    // warp w: rowg = w>>1 (rows rowg*8..+7), kg = w&1 (code half)
    const int warp = tid >> 5;
    const int lane = tid & 31;
    const int rowg = warp >> 1;
    const int kg   = warp & 1;
    const int kb   = kg * 256 + 2 * lane;   // codes: kb + 64*jj + {0,1}, jj=0..3

    unsigned long long acc[8][4];
    #pragma unroll
    for (int r = 0; r < 8; r++)
        #pragma unroll
        for (int j = 0; j < 4; j++) acc[r][j] = 0ULL;

    const float* arow = xs + rowg * 8;
    const unsigned long long* bbase = (const unsigned long long*)(wT + kb);

    #pragma unroll 4
    for (int c = 0; c < C_DIM; c++) {
        // 8 row values (broadcast loads)
        const float4 a0 = *(const float4*)(arow + c * 64);
        const float4 a1 = *(const float4*)(arow + c * 64 + 4);
        unsigned long long aa[8];
        aa[0] = pack2(a0.x); aa[1] = pack2(a0.y); aa[2] = pack2(a0.z); aa[3] = pack2(a0.w);
        aa[4] = pack2(a1.x); aa[5] = pack2(a1.y); aa[6] = pack2(a1.z); aa[7] = pack2(a1.w);
        // 4 code pairs (lane stride 8B -> conflict-free LDS.64)
        const unsigned long long* bp = bbase + (size_t)c * (WROW / 2);
        unsigned long long bb[4];
        #pragma unroll
        for (int j = 0; j < 4; j++) bb[j] = bp[32 * j];   // 64-float stride between jj chunks
        #pragma unroll
        for (int r = 0; r < 8; r++) {
            #pragma unroll
            for (int j = 0; j < 4; j++) fma2(acc[r][j], aa[r], bb[j]);
        }
    }

    // epilogue: distances (reference rounding), per-warp argmin, candidate write
    const float INF = __int_as_float(0x7f800000);
    #pragma unroll
    for (int r = 0; r < 8; r++) {
        const int row = rowg * 8 + r;
        const int n   = n0 + row;
        const float xn = xnorm[row];

        float best = INF; int bidx = 0;
        float* dptr = out + DIST_OFF + (size_t)n * K_CB + kb;
        #pragma unroll
        for (int j = 0; j < 4; j++) {
            float zlo, zhi; unpack2(acc[r][j], zlo, zhi);
            const int k0 = kb + 64 * j;
            float dlo = (xn + wnorm[k0])     - 2.0f * zlo;
            float dhi = (xn + wnorm[k0 + 1]) - 2.0f * zhi;
            dptr[64 * j]     = dlo;       // lanes contiguous -> coalesced
            dptr[64 * j + 1] = dhi;
            if (dlo < best) { best = dlo; bidx = k0; }      // increasing k order:
            if (dhi < best) { best = dhi; bidx = k0 + 1; }  // strict '<' keeps lowest index
        }
        // warp argmin, jnp tie-break = lowest index
        #pragma unroll
        for (int off = 16; off > 0; off >>= 1) {
            float ob = __shfl_xor_sync(0xffffffffu, best, off);
            int   oi = __shfl_xor_sync(0xffffffffu, bidx, off);
            if (ob < best || (ob == best && oi < bidx)) { best = ob; bidx = oi; }
        }
        if (lane == 0) { candb[row * 2 + kg] = best; candi[row * 2 + kg] = bidx; }
    }
    __syncthreads();

    // combine the two code-half candidates per row
    if (tid < TM) {
        float b0 = candb[tid * 2],     b1 = candb[tid * 2 + 1];
        int   i0 = candi[tid * 2],     i1 = candi[tid * 2 + 1];
        int bi = (b1 < b0) ? i1 : i0;   // tie -> kg0 (lower index)
        sidx[tid] = bi;
        const int n = n0 + tid;
        g_idx[n] = bi;
        out[EIDX_OFF + (size_t)n] = (float)bi;
    }
    __syncthreads();

    // encodings: write full one-hot rows (no separate memset pass)
    {
        float* ebase = out + ENC_OFF + (size_t)n0 * K_CB;
        #pragma unroll 4
        for (int i = tid; i < TM * K_CB; i += THREADS) {
            int row = i >> 9, k = i & 511;
            ebase[i] = (k == sidx[row]) ? 1.0f : 0.0f;
        }
    }

    // q_out tile (NCHW) with straight-through rounding; fused loss partial
    float s = 0.f;
    float* qbase = out + (size_t)b * (C_DIM * HW) + p0;
    #pragma unroll 2
    for (int i = tid; i < C_DIM * TM; i += THREADS) {
        int c = i >> 6, p = i & 63;
        float x = xs[c * 64 + p];
        float q = wT[c * WROW + sidx[p]];
        float d = q - x;
        qbase[(size_t)c * HW + p] = x + d;
        s = fmaf(d, d, s);
    }
    red[tid] = s;
    __syncthreads();
    #pragma unroll
    for (int off = 256; off > 0; off >>= 1) {
        if (tid < off) red[tid] += red[tid + off];
        __syncthreads();
    }
    if (tid == 0) g_lpart[blockIdx.x] = red[0];
}

// ---------------- finish kernel: loss + perplexity (single block, deterministic) ----------------
extern "C" __global__ void vq_finish(float* __restrict__ out)
{
    __shared__ int   hist[K_CB];
    __shared__ float red[K_CB];
    const int tid = threadIdx.x;
    hist[tid] = 0;
    __syncthreads();
    for (int i = tid; i < N_TOT; i += K_CB) atomicAdd(&hist[g_idx[i]], 1);
    __syncthreads();

    if (tid < B_DIM) {
        float s = 0.f;
        #pragma unroll
        for (int j = 0; j < 16; j++) s += g_lpart[tid * 16 + j];   // fixed order
        out[LOSS_OFF + tid] = 1.25f * (s * (1.0f / 65536.0f));
    }

    float p = (float)hist[tid] * (1.0f / 65536.0f);
    red[tid] = -p * logf(p + 1e-10f);
    __syncthreads();
    #pragma unroll
    for (int off = 256; off > 0; off >>= 1) {
        if (tid < off) red[tid] += red[tid + off];
        __syncthreads();
    }
    if (tid == 0) out[PERP_OFF] = expf(red[0]);
}

// ---------------- launch ----------------
extern "C" void kernel_launch(void* const* d_in, const int* in_sizes, int n_in,
                              void* d_out, int out_size)
{
    const float* inputs = (const float*)d_in[0];
    const float* weight = (const float*)d_in[1];
    float* out = (float*)d_out;

    if (out_size != OUT_TOTAL) return;

    cudaFuncSetAttribute(vq_main, cudaFuncAttributeMaxDynamicSharedMemorySize, SMEM_BYTES);

    vq_main<<<N_TOT / TM, THREADS, SMEM_BYTES>>>(inputs, weight, out);
    vq_finish<<<1, K_CB>>>(out);
}